// round 6
// baseline (speedup 1.0000x reference)
#include <cuda_runtime.h>
#include <cstdint>

// Rotation42d: per-sample rotation of (256, 3, 224, 224) fp32 by label in {0,1,2,3}.
// One block = one 32x32 tile position x 3 channels of one sample.
// Block (8,16): each thread handles 2 tile rows x 3 channels = 6 front-batched
// LDG.128 (deep MLP). Streaming cache hints; conflict-free smem transpose.

#define HW 224
#define TILES 7          // 224/32
#define ROW4 56          // 224/4 float4 per row
#define CH_STRIDE (HW * ROW4)   // float4 per channel plane = 12544

__global__ __launch_bounds__(128) void rot_kernel(
    const float4* __restrict__ x4,
    const int*    __restrict__ label,
    float4*       __restrict__ out4,
    float*        __restrict__ out_tail,   // may be null
    int                         n_tail)
{
    const int b   = blockIdx.z;          // sample 0..255
    const int lab = __ldg(label + b) & 3;

    const int bx = blockIdx.x;           // output tile col
    const int by = blockIdx.y;           // output tile row
    const int tx = threadIdx.x;          // 0..7   (float4 group within tile)
    const int ty = threadIdx.y;          // 0..15  (row pair selector)

    if (out_tail != nullptr) {
        if (bx == 0 && by == 0 && tx == 0 && ty == 0 && b < n_tail)
            out_tail[b] = (float)__ldg(label + b);
    }

    const float4* __restrict__ in = x4   + (size_t)b * (3 * CH_STRIDE);
    float4* __restrict__       o  = out4 + (size_t)b * (3 * CH_STRIDE);

    __shared__ float tile[3][32][33];    // +1 pad: conflict-free transposed reads

    const int r0 = ty;                   // first row handled
    const int r1 = ty + 16;              // second row handled

    if (lab == 0 || lab == 2) {
        const int h0 = by * 32 + r0;
        const int h1 = by * 32 + r1;
        const int g  = bx * 8 + tx;
        const int s0 = (lab == 0) ? (h0 * ROW4 + g) : ((HW - 1 - h0) * ROW4 + g);
        const int s1 = (lab == 0) ? (h1 * ROW4 + g) : ((HW - 1 - h1) * ROW4 + g);
        // 6 independent loads front-batched, then 6 stores
        const float4 a0 = __ldcs(in + 0 * CH_STRIDE + s0);
        const float4 a1 = __ldcs(in + 1 * CH_STRIDE + s0);
        const float4 a2 = __ldcs(in + 2 * CH_STRIDE + s0);
        const float4 b0 = __ldcs(in + 0 * CH_STRIDE + s1);
        const float4 b1 = __ldcs(in + 1 * CH_STRIDE + s1);
        const float4 b2 = __ldcs(in + 2 * CH_STRIDE + s1);
        const int d0 = h0 * ROW4 + g;
        const int d1 = h1 * ROW4 + g;
        __stcs(o + 0 * CH_STRIDE + d0, a0);
        __stcs(o + 1 * CH_STRIDE + d0, a1);
        __stcs(o + 2 * CH_STRIDE + d0, a2);
        __stcs(o + 0 * CH_STRIDE + d1, b0);
        __stcs(o + 1 * CH_STRIDE + d1, b1);
        __stcs(o + 2 * CH_STRIDE + d1, b2);
    } else {
        // r90 : tile[r][c] = in[bx*32+r][by*32+c]
        // r270: tile[r][c] = in[HW-1-(bx*32+r)][by*32+c]
        const int sr0 = (lab == 1) ? (bx * 32 + r0) : (HW - 1 - (bx * 32 + r0));
        const int sr1 = (lab == 1) ? (bx * 32 + r1) : (HW - 1 - (bx * 32 + r1));
        const int si0 = sr0 * ROW4 + (by * 8 + tx);
        const int si1 = sr1 * ROW4 + (by * 8 + tx);
        const float4 a0 = __ldcs(in + 0 * CH_STRIDE + si0);
        const float4 a1 = __ldcs(in + 1 * CH_STRIDE + si0);
        const float4 a2 = __ldcs(in + 2 * CH_STRIDE + si0);
        const float4 b0 = __ldcs(in + 0 * CH_STRIDE + si1);
        const float4 b1 = __ldcs(in + 1 * CH_STRIDE + si1);
        const float4 b2 = __ldcs(in + 2 * CH_STRIDE + si1);
        #pragma unroll
        for (int k = 0; k < 4; k++) {
            tile[0][r0][4 * tx + k] = ((const float*)&a0)[k];
            tile[1][r0][4 * tx + k] = ((const float*)&a1)[k];
            tile[2][r0][4 * tx + k] = ((const float*)&a2)[k];
            tile[0][r1][4 * tx + k] = ((const float*)&b0)[k];
            tile[1][r1][4 * tx + k] = ((const float*)&b1)[k];
            tile[2][r1][4 * tx + k] = ((const float*)&b2)[k];
        }
        __syncthreads();

        // out[(by*32+i)][bx*32+4g+k] = tile[4g+k][i], for i = r0 and r1
        const int g = tx;
        #pragma unroll
        for (int half = 0; half < 2; half++) {
            const int i = ty + half * 16;
            const int dst = (by * 32 + i) * ROW4 + (bx * 8 + g);
            #pragma unroll
            for (int ch = 0; ch < 3; ch++) {
                float4 w;
                w.x = tile[ch][4 * g + 0][i];
                w.y = tile[ch][4 * g + 1][i];
                w.z = tile[ch][4 * g + 2][i];
                w.w = tile[ch][4 * g + 3][i];
                __stcs(o + ch * CH_STRIDE + dst, w);
            }
        }
    }
}

extern "C" void kernel_launch(void* const* d_in, const int* in_sizes, int n_in,
                              void* d_out, int out_size)
{
    const float4* x     = (const float4*)d_in[0];
    const int*    label = (const int*)d_in[1];
    float4*       out   = (float4*)d_out;

    const int  n_label   = (n_in > 1) ? in_sizes[1] : 256;
    const long img_elems = 256L * 3L * HW * HW;  // 38,535,168

    float* out_tail = nullptr;
    int    n_tail   = 0;
    if ((long)out_size > img_elems) {
        const int tail = (int)((long)out_size - img_elems);
        n_tail   = tail < n_label ? tail : n_label;
        out_tail = (float*)d_out + img_elems;
    }

    dim3 grid(TILES, TILES, 256);
    dim3 block(8, 16);
    rot_kernel<<<grid, block>>>(x, label, out, out_tail, n_tail);
}

// round 9
// speedup vs baseline: 1.2534x; 1.2534x over previous
#include <cuda_runtime.h>
#include <cstdint>

// Rotation42d: per-sample rotation of (256, 3, 224, 224) fp32 by label in {0,1,2,3}.
// One block handles one 32x32 tile across ALL 3 channels of a sample
// (channels share the label) -> 3 independent LDG.128 per thread (MLP=3,
// measured sweet spot: MLP=1 -> 51.7us, MLP=3 -> 42.1us, MLP=6 -> 57.4us).
// All global traffic 128-bit, streaming cache hints (no reuse).

#define HW 224
#define TILES 7          // 224/32
#define ROW4 56          // 224/4 float4 per row
#define CH_STRIDE (HW * ROW4)   // float4 per channel plane = 12544

__global__ __launch_bounds__(256) void rot_kernel(
    const float4* __restrict__ x4,
    const int*    __restrict__ label,
    float4*       __restrict__ out4,
    float*        __restrict__ out_tail,   // may be null
    int                         n_tail)
{
    const int b   = blockIdx.z;          // sample 0..255
    const int lab = __ldg(label + b) & 3;

    const int bx = blockIdx.x;           // output tile col
    const int by = blockIdx.y;           // output tile row
    const int tx = threadIdx.x;          // 0..7   (float4 group within tile)
    const int ty = threadIdx.y;          // 0..31  (row within tile)

    if (out_tail != nullptr &&
        (bx | by | tx | ty) == 0 && b < n_tail) {
        out_tail[b] = (float)__ldg(label + b);
    }

    const float4* __restrict__ in = x4   + (size_t)b * (3 * CH_STRIDE);
    float4* __restrict__       o  = out4 + (size_t)b * (3 * CH_STRIDE);

    __shared__ float tile[3][32][33];    // +1 pad: conflict-free transposed reads

    if (lab == 0 || lab == 2) {
        const int h = by * 32 + ty;
        const int g = bx * 8 + tx;
        const int src = (lab == 0) ? (h * ROW4 + g) : ((HW - 1 - h) * ROW4 + g);
        const int dst = h * ROW4 + g;
        // 3 independent loads front-batched, then 3 stores
        const float4 v0 = __ldcs(in + src);
        const float4 v1 = __ldcs(in + CH_STRIDE + src);
        const float4 v2 = __ldcs(in + 2 * CH_STRIDE + src);
        __stcs(o + dst, v0);
        __stcs(o + CH_STRIDE + dst, v1);
        __stcs(o + 2 * CH_STRIDE + dst, v2);
    } else {
        // r90 : out[h][w] = in[w][h]         -> tile[r][c] = in[bx*32+r][by*32+c]
        // r270: out[h][w] = in[HW-1-w][h]    -> tile[r][c] = in[HW-1-(bx*32+r)][by*32+c]
        const int r = ty;
        const int src_row = (lab == 1) ? (bx * 32 + r)
                                       : (HW - 1 - (bx * 32 + r));
        const int sidx = src_row * ROW4 + (by * 8 + tx);
        const float4 v0 = __ldcs(in + sidx);
        const float4 v1 = __ldcs(in + CH_STRIDE + sidx);
        const float4 v2 = __ldcs(in + 2 * CH_STRIDE + sidx);
        #pragma unroll
        for (int k = 0; k < 4; k++) {
            tile[0][r][4 * tx + k] = ((const float*)&v0)[k];
            tile[1][r][4 * tx + k] = ((const float*)&v1)[k];
            tile[2][r][4 * tx + k] = ((const float*)&v2)[k];
        }
        __syncthreads();

        const int i = ty;
        const int g = tx;
        const int dst = (by * 32 + i) * ROW4 + (bx * 8 + g);
        #pragma unroll
        for (int ch = 0; ch < 3; ch++) {
            float4 w;
            w.x = tile[ch][4 * g + 0][i];
            w.y = tile[ch][4 * g + 1][i];
            w.z = tile[ch][4 * g + 2][i];
            w.w = tile[ch][4 * g + 3][i];
            __stcs(o + ch * CH_STRIDE + dst, w);
        }
    }
}

extern "C" void kernel_launch(void* const* d_in, const int* in_sizes, int n_in,
                              void* d_out, int out_size)
{
    const float4* x     = (const float4*)d_in[0];
    const int*    label = (const int*)d_in[1];
    float4*       out   = (float4*)d_out;

    const int  n_label   = (n_in > 1) ? in_sizes[1] : 256;
    const long img_elems = 256L * 3L * HW * HW;  // 38,535,168

    float* out_tail = nullptr;
    int    n_tail   = 0;
    if ((long)out_size > img_elems) {
        const int tail = (int)((long)out_size - img_elems);
        n_tail   = tail < n_label ? tail : n_label;
        out_tail = (float*)d_out + img_elems;
    }

    dim3 grid(TILES, TILES, 256);
    dim3 block(8, 32);
    rot_kernel<<<grid, block>>>(x, label, out, out_tail, n_tail);
}